// round 13
// baseline (speedup 1.0000x reference)
#include <cuda_runtime.h>
#include <cuda_bf16.h>
#include <stdint.h>
#include <math.h>

// Problem constants
#define NB   8192
#define DFT  256
#define RNK  16
#define AH   512
#define DCAT 2304
#define WSZ  (RNK * DFT * DFT)

// packed weight arena offsets (elements)
#define OFF_WG   0
#define OFF_W2   (256 * 512)
#define OFF_W3   (OFF_W2 + 256 * 768)
#define OFF_WA1  (OFF_W3 + 256 * 1024)
#define WARENA   (OFF_WA1 + 512 * 2304)

// ---------------------------------------------------------------------------
// Scratch
// ---------------------------------------------------------------------------
__device__ float g_p [NB * DFT];
__device__ float d2_p[NB * DFT];
__device__ float d3_p[NB * DFT];
__device__ float a1_g[NB * AH];
__device__ float beta_g[NB * RNK];

__device__ __nv_bfloat16 A_hi[3][NB * DFT];
__device__ __nv_bfloat16 A_lo[3][NB * DFT];
__device__ __nv_bfloat16 W_hi[3][WSZ];
__device__ __nv_bfloat16 W_lo[3][WSZ];
__device__ __nv_bfloat16 hcat_hi[NB * DCAT];
__device__ __nv_bfloat16 hcat_lo[NB * DCAT];
__device__ __nv_bfloat16 wcat_hi[WARENA];
__device__ __nv_bfloat16 wcat_lo[WARENA];

#define LDSM_X4(r0, r1, r2, r3, addr)                                         \
  asm volatile("ldmatrix.sync.aligned.m8n8.x4.shared.b16 {%0,%1,%2,%3}, [%4];\n" \
               : "=r"(r0), "=r"(r1), "=r"(r2), "=r"(r3) : "r"(addr))

#define MMA_BF16(c, a, b0, b1)                                                \
  asm volatile("mma.sync.aligned.m16n8k16.row.col.f32.bf16.bf16.f32 "         \
               "{%0,%1,%2,%3}, {%4,%5,%6,%7}, {%8,%9}, {%0,%1,%2,%3};\n"      \
               : "+f"((c)[0]), "+f"((c)[1]), "+f"((c)[2]), "+f"((c)[3])       \
               : "r"((a)[0]), "r"((a)[1]), "r"((a)[2]), "r"((a)[3]),          \
                 "r"(b0), "r"(b1))

// ---------------------------------------------------------------------------
// Elementwise splits
// ---------------------------------------------------------------------------
__global__ __launch_bounds__(256)
void splitw(const float* __restrict__ src, __nv_bfloat16* __restrict__ hi,
            __nv_bfloat16* __restrict__ lo, int n)
{
    const int i = blockIdx.x * 256 + threadIdx.x;
    if (i < n) {
        const float x = src[i];
        const __nv_bfloat16 h = __float2bfloat16(x);
        hi[i] = h;
        lo[i] = __float2bfloat16(x - __bfloat162float(h));
    }
}

__global__ __launch_bounds__(256)
void split_strided(const float* __restrict__ src, int cols, int off)
{
    const int i = blockIdx.x * 256 + threadIdx.x;
    const int row = i / cols, col = i - row * cols;
    const float x = src[i];
    const __nv_bfloat16 h = __float2bfloat16(x);
    const size_t d = (size_t)row * DCAT + off + col;
    hcat_hi[d] = h;
    hcat_lo[d] = __float2bfloat16(x - __bfloat162float(h));
}

// ---------------------------------------------------------------------------
// Shared GEMM body: bf16-split tensor-core GEMM (ldmatrix + 3-stage ring).
// ---------------------------------------------------------------------------
#define GKC    32
#define GPITCH 40
#define G_A    (128 * GPITCH)
#define GST    (4 * G_A)
#define GSMEM  (3 * GST * 2)

__device__ __forceinline__
void mma_gemm_body(const __nv_bfloat16* __restrict__ Ahi,
                   const __nv_bfloat16* __restrict__ Alo, int lda,
                   const __nv_bfloat16* __restrict__ Bhi,
                   const __nv_bfloat16* __restrict__ Blo,
                   const float* __restrict__ bias, float* __restrict__ C,
                   int N, int K, int relu, int bm, int bn, char* smraw)
{
    __nv_bfloat16* sm = (__nv_bfloat16*)smraw;
    const int tid  = threadIdx.x;
    const int lane = tid & 31, wid = tid >> 5;
    const int wm = wid & 3, wn = wid >> 2;
    const int g  = lane >> 2, tg = lane & 3;

    const int nstage = K / GKC;

    auto issue = [&](int s) {
        const int k0 = s * GKC;
        __nv_bfloat16* base = sm + (size_t)(s % 3) * GST;
        #pragma unroll
        for (int i = 0; i < 2; ++i) {
            const int c = i * 256 + tid;
            const int row = c >> 2, seg = (c & 3) << 3;
            const size_t ga = (size_t)(bm + row) * lda + k0 + seg;
            const size_t gb = (size_t)(bn + row) * K + k0 + seg;
            uint32_t d;
            d = (uint32_t)__cvta_generic_to_shared(base + row * GPITCH + seg);
            asm volatile("cp.async.cg.shared.global [%0], [%1], 16;\n"
                         :: "r"(d), "l"(Ahi + ga));
            d = (uint32_t)__cvta_generic_to_shared(base + G_A + row * GPITCH + seg);
            asm volatile("cp.async.cg.shared.global [%0], [%1], 16;\n"
                         :: "r"(d), "l"(Alo + ga));
            d = (uint32_t)__cvta_generic_to_shared(base + 2 * G_A + row * GPITCH + seg);
            asm volatile("cp.async.cg.shared.global [%0], [%1], 16;\n"
                         :: "r"(d), "l"(Bhi + gb));
            d = (uint32_t)__cvta_generic_to_shared(base + 3 * G_A + row * GPITCH + seg);
            asm volatile("cp.async.cg.shared.global [%0], [%1], 16;\n"
                         :: "r"(d), "l"(Blo + gb));
        }
    };

    issue(0);
    asm volatile("cp.async.commit_group;\n" ::: "memory");
    if (nstage > 1) {
        issue(1);
        asm volatile("cp.async.commit_group;\n" ::: "memory");
    }

    const int lq = lane & 7, lh = (lane >> 3) & 1, lk = lane >> 4;
    int a_off[2], b_off[4];
    #pragma unroll
    for (int mf = 0; mf < 2; ++mf)
        a_off[mf] = ((wm * 32 + mf * 16 + lq + lh * 8) * GPITCH + lk * 8) * 2;
    #pragma unroll
    for (int n2 = 0; n2 < 4; ++n2)
        b_off[n2] = ((wn * 64 + n2 * 16 + lq + lh * 8) * GPITCH + lk * 8) * 2;

    float acc[2][8][4];
    #pragma unroll
    for (int mf = 0; mf < 2; ++mf)
        #pragma unroll
        for (int nf = 0; nf < 8; ++nf)
            #pragma unroll
            for (int e = 0; e < 4; ++e) acc[mf][nf][e] = 0.f;

    for (int s = 0; s < nstage; ++s) {
        if (s + 2 < nstage) {
            asm volatile("cp.async.wait_group 1;\n" ::: "memory");
            __syncthreads();
            issue(s + 2);
            asm volatile("cp.async.commit_group;\n" ::: "memory");
        } else {
            asm volatile("cp.async.wait_group 0;\n" ::: "memory");
            __syncthreads();
        }

        const uint32_t sb = (uint32_t)__cvta_generic_to_shared(
                                sm + (size_t)(s % 3) * GST);
        const uint32_t ah_b = sb;
        const uint32_t al_b = sb + 2 * G_A;
        const uint32_t bh_b = sb + 4 * G_A;
        const uint32_t bl_b = sb + 6 * G_A;

        #pragma unroll
        for (int ks = 0; ks < GKC; ks += 16) {
            uint32_t ah[2][4], al[2][4];
            #pragma unroll
            for (int mf = 0; mf < 2; ++mf) {
                LDSM_X4(ah[mf][0], ah[mf][1], ah[mf][2], ah[mf][3],
                        ah_b + a_off[mf] + ks * 2);
                LDSM_X4(al[mf][0], al[mf][1], al[mf][2], al[mf][3],
                        al_b + a_off[mf] + ks * 2);
            }
            uint32_t bh[4][4], bl[4][4];
            #pragma unroll
            for (int n2 = 0; n2 < 4; ++n2) {
                LDSM_X4(bh[n2][0], bh[n2][1], bh[n2][2], bh[n2][3],
                        bh_b + b_off[n2] + ks * 2);
                LDSM_X4(bl[n2][0], bl[n2][1], bl[n2][2], bl[n2][3],
                        bl_b + b_off[n2] + ks * 2);
            }
            #pragma unroll
            for (int mf = 0; mf < 2; ++mf) {
                #pragma unroll
                for (int n2 = 0; n2 < 4; ++n2) {
                    MMA_BF16(acc[mf][n2 * 2 + 0], ah[mf], bh[n2][0], bh[n2][2]);
                    MMA_BF16(acc[mf][n2 * 2 + 1], ah[mf], bh[n2][1], bh[n2][3]);
                    MMA_BF16(acc[mf][n2 * 2 + 0], ah[mf], bl[n2][0], bl[n2][2]);
                    MMA_BF16(acc[mf][n2 * 2 + 1], ah[mf], bl[n2][1], bl[n2][3]);
                    MMA_BF16(acc[mf][n2 * 2 + 0], al[mf], bh[n2][0], bh[n2][2]);
                    MMA_BF16(acc[mf][n2 * 2 + 1], al[mf], bh[n2][1], bh[n2][3]);
                }
            }
        }
    }

    #pragma unroll
    for (int mf = 0; mf < 2; ++mf) {
        const int row0 = bm + wm * 32 + mf * 16 + g;
        #pragma unroll
        for (int nf = 0; nf < 8; ++nf) {
            const int col = bn + wn * 64 + nf * 8 + tg * 2;
            const float b0 = bias[col], b1 = bias[col + 1];
            float v0 = acc[mf][nf][0] + b0, v1 = acc[mf][nf][1] + b1;
            float v2 = acc[mf][nf][2] + b0, v3 = acc[mf][nf][3] + b1;
            if (relu) {
                v0 = fmaxf(v0, 0.f); v1 = fmaxf(v1, 0.f);
                v2 = fmaxf(v2, 0.f); v3 = fmaxf(v3, 0.f);
            }
            *(float2*)&C[(size_t)row0 * N + col]       = make_float2(v0, v1);
            *(float2*)&C[(size_t)(row0 + 8) * N + col] = make_float2(v2, v3);
        }
    }
}

__global__ __launch_bounds__(256, 1)
void mma_gemm2(const __nv_bfloat16* __restrict__ Ahi,
               const __nv_bfloat16* __restrict__ Alo, int lda,
               const __nv_bfloat16* __restrict__ Bhi,
               const __nv_bfloat16* __restrict__ Blo,
               const float* __restrict__ bias, float* __restrict__ C,
               int N, int K, int relu)
{
    extern __shared__ __align__(16) char smraw[];
    mma_gemm_body(Ahi, Alo, lda, Bhi, Blo, bias, C, N, K, relu,
                  blockIdx.y << 7, blockIdx.x << 7, smraw);
}

// merged 3-modality projection: grid (2, 64, 3)
__global__ __launch_bounds__(256, 1)
void proj3(const __nv_bfloat16* __restrict__ hh,
           const __nv_bfloat16* __restrict__ hl,
           const __nv_bfloat16* __restrict__ wch,
           const __nv_bfloat16* __restrict__ wcl,
           const float* __restrict__ bg, const float* __restrict__ b2,
           const float* __restrict__ b3,
           float* __restrict__ gp, float* __restrict__ d2p,
           float* __restrict__ d3p)
{
    extern __shared__ __align__(16) char smraw[];
    const int m = blockIdx.z;
    const __nv_bfloat16 *Ah, *Al, *Bh, *Bl;
    const float* bias; float* C; int K;
    if (m == 0) { Ah = hh;        Al = hl;        Bh = wch + OFF_WG; Bl = wcl + OFF_WG;
                  bias = bg; C = gp;  K = 512; }
    else if (m == 1) { Ah = hh + 512;  Al = hl + 512;  Bh = wch + OFF_W2; Bl = wcl + OFF_W2;
                  bias = b2; C = d2p; K = 768; }
    else { Ah = hh + 1280; Al = hl + 1280; Bh = wch + OFF_W3; Bl = wcl + OFF_W3;
                  bias = b3; C = d3p; K = 1024; }
    mma_gemm_body(Ah, Al, DCAT, Bh, Bl, bias, C, 256, K, 0,
                  blockIdx.y << 7, blockIdx.x << 7, smraw);
}

// ---------------------------------------------------------------------------
// LayerNorm + ReLU + bf16 hi/lo split.
// ---------------------------------------------------------------------------
__global__ __launch_bounds__(256)
void ln_relu(const float* __restrict__ lgw, const float* __restrict__ lgb,
             const float* __restrict__ l2w, const float* __restrict__ l2b,
             const float* __restrict__ l3w, const float* __restrict__ l3b)
{
    const int idx = blockIdx.x;
    const int mod = idx >> 13;
    const int row = idx & 8191;
    const float* buf; const float* w; const float* b;
    if (mod == 0)      { buf = g_p;  w = lgw; b = lgb; }
    else if (mod == 1) { buf = d2_p; w = l2w; b = l2b; }
    else               { buf = d3_p; w = l3w; b = l3b; }

    const int t = threadIdx.x;
    const float v = buf[(size_t)row * DFT + t];
    float s = v, q = v * v;
    #pragma unroll
    for (int o = 16; o > 0; o >>= 1) {
        s += __shfl_down_sync(0xffffffffu, s, o);
        q += __shfl_down_sync(0xffffffffu, q, o);
    }
    __shared__ float ss[8], qq[8];
    __shared__ float mu_s, rstd_s;
    if ((t & 31) == 0) { ss[t >> 5] = s; qq[t >> 5] = q; }
    __syncthreads();
    if (t == 0) {
        float S = 0.f, Q = 0.f;
        #pragma unroll
        for (int i = 0; i < 8; ++i) { S += ss[i]; Q += qq[i]; }
        const float mu  = S * (1.f / 256.f);
        const float var = Q * (1.f / 256.f) - mu * mu;
        mu_s = mu; rstd_s = rsqrtf(var + 1e-5f);
    }
    __syncthreads();
    const float o  = (v - mu_s) * rstd_s * w[t] + b[t];
    const float oo = fmaxf(o, 0.f);
    const __nv_bfloat16 hi = __float2bfloat16(oo);
    A_hi[mod][(size_t)row * DFT + t] = hi;
    A_lo[mod][(size_t)row * DFT + t] = __float2bfloat16(oo - __bfloat162float(hi));
}

// ---------------------------------------------------------------------------
// beta = softmax(a1 @ Wa2.T + ba2).
// ---------------------------------------------------------------------------
__global__ __launch_bounds__(128)
void beta_kernel(const float* __restrict__ Wa2, const float* __restrict__ ba2)
{
    const int row = blockIdx.x;
    __shared__ float sh[AH];
    __shared__ float logits[RNK];
    const int t = threadIdx.x;
    #pragma unroll
    for (int i = 0; i < 4; ++i)
        sh[t + i * 128] = a1_g[(size_t)row * AH + t + i * 128];
    __syncthreads();

    const int r = t >> 3;
    const int l = t & 7;
    float s = 0.f;
    for (int j = l; j < AH; j += 8)
        s = fmaf(sh[j], Wa2[r * AH + j], s);
    s += __shfl_down_sync(0xffffffffu, s, 4);
    s += __shfl_down_sync(0xffffffffu, s, 2);
    s += __shfl_down_sync(0xffffffffu, s, 1);
    if (l == 0) logits[r] = s + ba2[r];
    __syncthreads();
    if (t == 0) {
        float mx = logits[0];
        #pragma unroll
        for (int i = 1; i < RNK; ++i) mx = fmaxf(mx, logits[i]);
        float e[RNK], den = 0.f;
        #pragma unroll
        for (int i = 0; i < RNK; ++i) { e[i] = expf(logits[i] - mx); den += e[i]; }
        const float inv = 1.f / den;
        #pragma unroll
        for (int i = 0; i < RNK; ++i)
            beta_g[(size_t)row * RNK + i] = e[i] * inv;
    }
}

// ---------------------------------------------------------------------------
// fuse_mma4: trilinear + beta contraction.
// 256 threads, 8 warps (4m x 2n), warp tile 32x64, block tile 128x128.
// 2-stage ring (KC=64), pitch-72 smem, z accumulated in SMEM (no global RMW).
// ---------------------------------------------------------------------------
#define F4PITCH 72
#define F4_A    (128 * F4PITCH)           // 9216 elems per array
#define F4STG   (4 * F4_A)                // elems per stage
#define F4STGB  (F4STG * 2)               // 73728 bytes
#define F4ZPIT  132
#define F4Z     (128 * F4ZPIT * 4)        // 67584 bytes
#define F4SMEM  (2 * F4STGB + F4Z)        // 215040 bytes
#define F4NST   (RNK * 3 * 4)             // 192 stages

__global__ __launch_bounds__(256, 1)
void fuse_mma4(float* __restrict__ z)
{
    extern __shared__ __align__(16) char smraw[];
    __nv_bfloat16* sm = (__nv_bfloat16*)smraw;
    float* zs = (float*)(smraw + 2 * F4STGB);
    __shared__ float Bes[128][17];

    const int bm   = blockIdx.y << 7;
    const int bn   = blockIdx.x << 7;
    const int tid  = threadIdx.x;
    const int lane = tid & 31, wid = tid >> 5;
    const int wm   = wid & 3,  wn  = wid >> 2;     // 4 x 2 warps
    const int g    = lane >> 2, tg = lane & 3;

    for (int i = tid; i < 128 * RNK; i += 256)
        Bes[i >> 4][i & 15] = beta_g[(size_t)(bm + (i >> 4)) * RNK + (i & 15)];

    auto issue = [&](int s) {
        const int r2  = s / 12;
        const int rem = s % 12;
        const int m2  = rem >> 2;
        const int kc  = (rem & 3) << 6;
        __nv_bfloat16* base = sm + (size_t)(s & 1) * F4STG;
        #pragma unroll
        for (int i = 0; i < 16; ++i) {
            const int c   = i * 256 + tid;       // 0..4095
            const int arr = c >> 10;
            const int idx = c & 1023;
            const int row = idx >> 3, seg = (idx & 7) << 3;
            __nv_bfloat16* dst = base + arr * F4_A + row * F4PITCH + seg;
            const __nv_bfloat16* src;
            if (arr == 0)      src = &A_hi[m2][(size_t)(bm + row) * DFT + kc + seg];
            else if (arr == 1) src = &A_lo[m2][(size_t)(bm + row) * DFT + kc + seg];
            else if (arr == 2) src = &W_hi[m2][(size_t)(r2 * DFT + bn + row) * DFT + kc + seg];
            else               src = &W_lo[m2][(size_t)(r2 * DFT + bn + row) * DFT + kc + seg];
            uint32_t d = (uint32_t)__cvta_generic_to_shared(dst);
            asm volatile("cp.async.cg.shared.global [%0], [%1], 16;\n"
                         :: "r"(d), "l"(src));
        }
    };

    issue(0);
    asm volatile("cp.async.commit_group;\n" ::: "memory");

    const int lq = lane & 7, lh = (lane >> 3) & 1, lk = lane >> 4;
    int a_off[2], b_off[4];
    #pragma unroll
    for (int mf = 0; mf < 2; ++mf)
        a_off[mf] = ((wm * 32 + mf * 16 + lq + lh * 8) * F4PITCH + lk * 8) * 2;
    #pragma unroll
    for (int n2 = 0; n2 < 4; ++n2)
        b_off[n2] = ((wn * 64 + n2 * 16 + lq + lh * 8) * F4PITCH + lk * 8) * 2;

    float acc[2][8][4], prod[2][8][4];
    #pragma unroll
    for (int mf = 0; mf < 2; ++mf)
        #pragma unroll
        for (int nf = 0; nf < 8; ++nf)
            #pragma unroll
            for (int e = 0; e < 4; ++e) acc[mf][nf][e] = 0.f;

    int s = 0;
    for (int r = 0; r < RNK; ++r) {
        #pragma unroll
        for (int mI = 0; mI < 3; ++mI) {
            for (int c4 = 0; c4 < 4; ++c4, ++s) {
                // 2-stage ring: keep next stage in flight
                if (s + 1 < F4NST) {
                    issue(s + 1);
                    asm volatile("cp.async.commit_group;\n" ::: "memory");
                    asm volatile("cp.async.wait_group 1;\n" ::: "memory");
                } else {
                    asm volatile("cp.async.wait_group 0;\n" ::: "memory");
                }
                __syncthreads();

                const uint32_t sb = (uint32_t)__cvta_generic_to_shared(
                                        sm + (size_t)(s & 1) * F4STG);
                const uint32_t ah_b = sb;
                const uint32_t al_b = sb + 2 * F4_A;
                const uint32_t bh_b = sb + 4 * F4_A;
                const uint32_t bl_b = sb + 6 * F4_A;

                #pragma unroll
                for (int ks = 0; ks < 64; ks += 16) {
                    uint32_t ah[2][4], al[2][4];
                    #pragma unroll
                    for (int mf = 0; mf < 2; ++mf) {
                        LDSM_X4(ah[mf][0], ah[mf][1], ah[mf][2], ah[mf][3],
                                ah_b + a_off[mf] + ks * 2);
                        LDSM_X4(al[mf][0], al[mf][1], al[mf][2], al[mf][3],
                                al_b + a_off[mf] + ks * 2);
                    }
                    uint32_t bh[4][4], bl[4][4];
                    #pragma unroll
                    for (int n2 = 0; n2 < 4; ++n2) {
                        LDSM_X4(bh[n2][0], bh[n2][1], bh[n2][2], bh[n2][3],
                                bh_b + b_off[n2] + ks * 2);
                        LDSM_X4(bl[n2][0], bl[n2][1], bl[n2][2], bl[n2][3],
                                bl_b + b_off[n2] + ks * 2);
                    }
                    #pragma unroll
                    for (int mf = 0; mf < 2; ++mf) {
                        #pragma unroll
                        for (int n2 = 0; n2 < 4; ++n2) {
                            MMA_BF16(acc[mf][n2 * 2 + 0], ah[mf], bh[n2][0], bh[n2][2]);
                            MMA_BF16(acc[mf][n2 * 2 + 1], ah[mf], bh[n2][1], bh[n2][3]);
                            MMA_BF16(acc[mf][n2 * 2 + 0], ah[mf], bl[n2][0], bl[n2][2]);
                            MMA_BF16(acc[mf][n2 * 2 + 1], ah[mf], bl[n2][1], bl[n2][3]);
                            MMA_BF16(acc[mf][n2 * 2 + 0], al[mf], bh[n2][0], bh[n2][2]);
                            MMA_BF16(acc[mf][n2 * 2 + 1], al[mf], bh[n2][1], bh[n2][3]);
                        }
                    }
                }
                __syncthreads();   // all reads of slot (s&1) done before re-fill
            }
            if (mI == 0) {
                #pragma unroll
                for (int mf = 0; mf < 2; ++mf)
                    #pragma unroll
                    for (int nf = 0; nf < 8; ++nf)
                        #pragma unroll
                        for (int e = 0; e < 4; ++e)
                            { prod[mf][nf][e] = acc[mf][nf][e]; acc[mf][nf][e] = 0.f; }
            } else if (mI == 1) {
                #pragma unroll
                for (int mf = 0; mf < 2; ++mf)
                    #pragma unroll
                    for (int nf = 0; nf < 8; ++nf)
                        #pragma unroll
                        for (int e = 0; e < 4; ++e)
                            { prod[mf][nf][e] *= acc[mf][nf][e]; acc[mf][nf][e] = 0.f; }
            } else {
                // rank contribution -> smem z accumulator (thread-exclusive)
                #pragma unroll
                for (int mf = 0; mf < 2; ++mf) {
                    const int rt = wm * 32 + mf * 16 + g;
                    const float b0 = Bes[rt][r];
                    const float b1 = Bes[rt + 8][r];
                    #pragma unroll
                    for (int nf = 0; nf < 8; ++nf) {
                        const int ct = wn * 64 + nf * 8 + tg * 2;
                        float* p0 = zs + rt * F4ZPIT + ct;
                        float* p1 = zs + (rt + 8) * F4ZPIT + ct;
                        const float v0 = b0 * prod[mf][nf][0] * acc[mf][nf][0];
                        const float v1 = b0 * prod[mf][nf][1] * acc[mf][nf][1];
                        const float v2 = b1 * prod[mf][nf][2] * acc[mf][nf][2];
                        const float v3 = b1 * prod[mf][nf][3] * acc[mf][nf][3];
                        if (r == 0) {
                            p0[0] = v0; p0[1] = v1; p1[0] = v2; p1[1] = v3;
                        } else {
                            p0[0] += v0; p0[1] += v1; p1[0] += v2; p1[1] += v3;
                        }
                        #pragma unroll
                        for (int e = 0; e < 4; ++e) acc[mf][nf][e] = 0.f;
                    }
                }
            }
        }
    }

    // epilogue: smem z -> global
    __syncthreads();
    for (int i = tid; i < 128 * 32; i += 256) {
        const int row = i >> 5, c4 = (i & 31) << 2;
        const float4 v = *(const float4*)(zs + row * F4ZPIT + c4);
        *(float4*)&z[(size_t)(bm + row) * DFT + bn + c4] = v;
    }
}

// ---------------------------------------------------------------------------
// Host launcher (graph-capturable; event-forked side stream)
// ---------------------------------------------------------------------------
extern "C" void kernel_launch(void* const* d_in, const int* in_sizes, int n_in,
                              void* d_out, int out_size)
{
    const float* h_g  = (const float*)d_in[0];
    const float* h_2d = (const float*)d_in[1];
    const float* h_3d = (const float*)d_in[2];
    const float* Wg   = (const float*)d_in[3];
    const float* bg   = (const float*)d_in[4];
    const float* W2   = (const float*)d_in[5];
    const float* b2   = (const float*)d_in[6];
    const float* W3   = (const float*)d_in[7];
    const float* b3   = (const float*)d_in[8];
    const float* lgw  = (const float*)d_in[9];
    const float* lgb  = (const float*)d_in[10];
    const float* l2w  = (const float*)d_in[11];
    const float* l2b  = (const float*)d_in[12];
    const float* l3w  = (const float*)d_in[13];
    const float* l3b  = (const float*)d_in[14];
    const float* U    = (const float*)d_in[15];
    const float* V    = (const float*)d_in[16];
    const float* S    = (const float*)d_in[17];
    const float* Wa1  = (const float*)d_in[18];
    const float* ba1  = (const float*)d_in[19];
    const float* Wa2  = (const float*)d_in[20];
    const float* ba2  = (const float*)d_in[21];
    float* z = (float*)d_out;

    float *gp, *d2p, *d3p, *a1p;
    cudaGetSymbolAddress((void**)&gp,  g_p);
    cudaGetSymbolAddress((void**)&d2p, d2_p);
    cudaGetSymbolAddress((void**)&d3p, d3_p);
    cudaGetSymbolAddress((void**)&a1p, a1_g);
    __nv_bfloat16 *whi, *wlo, *hh, *hl, *wch, *wcl;
    cudaGetSymbolAddress((void**)&whi, W_hi);
    cudaGetSymbolAddress((void**)&wlo, W_lo);
    cudaGetSymbolAddress((void**)&hh,  hcat_hi);
    cudaGetSymbolAddress((void**)&hl,  hcat_lo);
    cudaGetSymbolAddress((void**)&wch, wcat_hi);
    cudaGetSymbolAddress((void**)&wcl, wcat_lo);

    static int inited = 0;
    static cudaStream_t s1;
    static cudaEvent_t evF, evA, evJ;
    if (!inited) {
        cudaFuncSetAttribute(fuse_mma4, cudaFuncAttributeMaxDynamicSharedMemorySize,
                             F4SMEM);
        cudaFuncSetAttribute(mma_gemm2, cudaFuncAttributeMaxDynamicSharedMemorySize,
                             GSMEM);
        cudaFuncSetAttribute(proj3, cudaFuncAttributeMaxDynamicSharedMemorySize,
                             GSMEM);
        cudaStreamCreateWithFlags(&s1, cudaStreamNonBlocking);
        cudaEventCreateWithFlags(&evF, cudaEventDisableTiming);
        cudaEventCreateWithFlags(&evA, cudaEventDisableTiming);
        cudaEventCreateWithFlags(&evJ, cudaEventDisableTiming);
        inited = 1;
    }

    // ---- main stream: input (hcat) splits ----
    cudaEventRecord(evF, 0);
    split_strided<<<NB * 512  / 256, 256>>>(h_g,  512,  0);
    split_strided<<<NB * 768  / 256, 256>>>(h_2d, 768,  512);
    split_strided<<<NB * 1024 / 256, 256>>>(h_3d, 1024, 1280);
    cudaEventRecord(evA, 0);

    // ---- side stream: Wa1 split, Wa1 GEMM, beta ----
    cudaStreamWaitEvent(s1, evF, 0);
    splitw<<<(512 * 2304) / 256, 256, 0, s1>>>(Wa1, wch + OFF_WA1, wcl + OFF_WA1,
                                               512 * 2304);
    cudaStreamWaitEvent(s1, evA, 0);
    mma_gemm2<<<dim3(4, 64), 256, GSMEM, s1>>>(hh, hl, DCAT,
        wch + OFF_WA1, wcl + OFF_WA1, ba1, a1p, 512, 2304, 1);
    beta_kernel<<<NB, 128, 0, s1>>>(Wa2, ba2);
    cudaEventRecord(evJ, s1);

    // ---- main stream: U/V/S splits, projection weights, merged proj, LN ----
    splitw<<<WSZ / 256, 256>>>(U, whi + 0 * WSZ, wlo + 0 * WSZ, WSZ);
    splitw<<<WSZ / 256, 256>>>(V, whi + 1 * WSZ, wlo + 1 * WSZ, WSZ);
    splitw<<<WSZ / 256, 256>>>(S, whi + 2 * WSZ, wlo + 2 * WSZ, WSZ);
    splitw<<<(256 * 512)  / 256, 256>>>(Wg,  wch + OFF_WG,  wcl + OFF_WG,  256 * 512);
    splitw<<<(256 * 768)  / 256, 256>>>(W2,  wch + OFF_W2,  wcl + OFF_W2,  256 * 768);
    splitw<<<(256 * 1024) / 256, 256>>>(W3,  wch + OFF_W3,  wcl + OFF_W3,  256 * 1024);
    proj3<<<dim3(2, 64, 3), 256, GSMEM>>>(hh, hl, wch, wcl, bg, b2, b3,
                                          gp, d2p, d3p);
    ln_relu<<<3 * NB, 256>>>(lgw, lgb, l2w, l2b, l3w, l3b);

    // ---- join and run the fused trilinear (128 CTAs, one wave) ----
    cudaStreamWaitEvent(0, evJ, 0);
    fuse_mma4<<<dim3(2, 64), 256, F4SMEM>>>(z);
}

// round 15
// speedup vs baseline: 1.0702x; 1.0702x over previous
#include <cuda_runtime.h>
#include <cuda_bf16.h>
#include <stdint.h>
#include <math.h>

// Problem constants
#define NB   8192
#define DFT  256
#define RNK  16
#define AH   512
#define DCAT 2304
#define WSZ  (RNK * DFT * DFT)

// packed weight arena offsets (elements)
#define OFF_WG   0
#define OFF_W2   (256 * 512)
#define OFF_W3   (OFF_W2 + 256 * 768)
#define OFF_WA1  (OFF_W3 + 256 * 1024)
#define WARENA   (OFF_WA1 + 512 * 2304)

// ---------------------------------------------------------------------------
// Scratch
// ---------------------------------------------------------------------------
__device__ float g_p [NB * DFT];
__device__ float d2_p[NB * DFT];
__device__ float d3_p[NB * DFT];
__device__ float a1_g[NB * AH];
__device__ float beta_g[NB * RNK];

__device__ __nv_bfloat16 A_hi[3][NB * DFT];
__device__ __nv_bfloat16 A_lo[3][NB * DFT];
__device__ __nv_bfloat16 W_hi[3][WSZ];
__device__ __nv_bfloat16 W_lo[3][WSZ];
__device__ __nv_bfloat16 hcat_hi[NB * DCAT];
__device__ __nv_bfloat16 hcat_lo[NB * DCAT];
__device__ __nv_bfloat16 wcat_hi[WARENA];
__device__ __nv_bfloat16 wcat_lo[WARENA];

#define LDSM_X4(r0, r1, r2, r3, addr)                                         \
  asm volatile("ldmatrix.sync.aligned.m8n8.x4.shared.b16 {%0,%1,%2,%3}, [%4];\n" \
               : "=r"(r0), "=r"(r1), "=r"(r2), "=r"(r3) : "r"(addr))

#define MMA_BF16(c, a, b0, b1)                                                \
  asm volatile("mma.sync.aligned.m16n8k16.row.col.f32.bf16.bf16.f32 "         \
               "{%0,%1,%2,%3}, {%4,%5,%6,%7}, {%8,%9}, {%0,%1,%2,%3};\n"      \
               : "+f"((c)[0]), "+f"((c)[1]), "+f"((c)[2]), "+f"((c)[3])       \
               : "r"((a)[0]), "r"((a)[1]), "r"((a)[2]), "r"((a)[3]),          \
                 "r"(b0), "r"(b1))

// ---------------------------------------------------------------------------
// Elementwise splits
// ---------------------------------------------------------------------------
__global__ __launch_bounds__(256)
void splitw(const float* __restrict__ src, __nv_bfloat16* __restrict__ hi,
            __nv_bfloat16* __restrict__ lo, int n)
{
    const int i = blockIdx.x * 256 + threadIdx.x;
    if (i < n) {
        const float x = src[i];
        const __nv_bfloat16 h = __float2bfloat16(x);
        hi[i] = h;
        lo[i] = __float2bfloat16(x - __bfloat162float(h));
    }
}

__global__ __launch_bounds__(256)
void split_strided(const float* __restrict__ src, int cols, int off)
{
    const int i = blockIdx.x * 256 + threadIdx.x;
    const int row = i / cols, col = i - row * cols;
    const float x = src[i];
    const __nv_bfloat16 h = __float2bfloat16(x);
    const size_t d = (size_t)row * DCAT + off + col;
    hcat_hi[d] = h;
    hcat_lo[d] = __float2bfloat16(x - __bfloat162float(h));
}

// ---------------------------------------------------------------------------
// Shared GEMM body: bf16-split tensor-core GEMM (ldmatrix + 3-stage ring).
// ---------------------------------------------------------------------------
#define GKC    32
#define GPITCH 40
#define G_A    (128 * GPITCH)
#define GST    (4 * G_A)
#define GSMEM  (3 * GST * 2)

__device__ __forceinline__
void mma_gemm_body(const __nv_bfloat16* __restrict__ Ahi,
                   const __nv_bfloat16* __restrict__ Alo, int lda,
                   const __nv_bfloat16* __restrict__ Bhi,
                   const __nv_bfloat16* __restrict__ Blo,
                   const float* __restrict__ bias, float* __restrict__ C,
                   int N, int K, int relu, int bm, int bn, char* smraw)
{
    __nv_bfloat16* sm = (__nv_bfloat16*)smraw;
    const int tid  = threadIdx.x;
    const int lane = tid & 31, wid = tid >> 5;
    const int wm = wid & 3, wn = wid >> 2;
    const int g  = lane >> 2, tg = lane & 3;

    const int nstage = K / GKC;

    auto issue = [&](int s) {
        const int k0 = s * GKC;
        __nv_bfloat16* base = sm + (size_t)(s % 3) * GST;
        #pragma unroll
        for (int i = 0; i < 2; ++i) {
            const int c = i * 256 + tid;
            const int row = c >> 2, seg = (c & 3) << 3;
            const size_t ga = (size_t)(bm + row) * lda + k0 + seg;
            const size_t gb = (size_t)(bn + row) * K + k0 + seg;
            uint32_t d;
            d = (uint32_t)__cvta_generic_to_shared(base + row * GPITCH + seg);
            asm volatile("cp.async.cg.shared.global [%0], [%1], 16;\n"
                         :: "r"(d), "l"(Ahi + ga));
            d = (uint32_t)__cvta_generic_to_shared(base + G_A + row * GPITCH + seg);
            asm volatile("cp.async.cg.shared.global [%0], [%1], 16;\n"
                         :: "r"(d), "l"(Alo + ga));
            d = (uint32_t)__cvta_generic_to_shared(base + 2 * G_A + row * GPITCH + seg);
            asm volatile("cp.async.cg.shared.global [%0], [%1], 16;\n"
                         :: "r"(d), "l"(Bhi + gb));
            d = (uint32_t)__cvta_generic_to_shared(base + 3 * G_A + row * GPITCH + seg);
            asm volatile("cp.async.cg.shared.global [%0], [%1], 16;\n"
                         :: "r"(d), "l"(Blo + gb));
        }
    };

    issue(0);
    asm volatile("cp.async.commit_group;\n" ::: "memory");
    if (nstage > 1) {
        issue(1);
        asm volatile("cp.async.commit_group;\n" ::: "memory");
    }

    const int lq = lane & 7, lh = (lane >> 3) & 1, lk = lane >> 4;
    int a_off[2], b_off[4];
    #pragma unroll
    for (int mf = 0; mf < 2; ++mf)
        a_off[mf] = ((wm * 32 + mf * 16 + lq + lh * 8) * GPITCH + lk * 8) * 2;
    #pragma unroll
    for (int n2 = 0; n2 < 4; ++n2)
        b_off[n2] = ((wn * 64 + n2 * 16 + lq + lh * 8) * GPITCH + lk * 8) * 2;

    float acc[2][8][4];
    #pragma unroll
    for (int mf = 0; mf < 2; ++mf)
        #pragma unroll
        for (int nf = 0; nf < 8; ++nf)
            #pragma unroll
            for (int e = 0; e < 4; ++e) acc[mf][nf][e] = 0.f;

    for (int s = 0; s < nstage; ++s) {
        if (s + 2 < nstage) {
            asm volatile("cp.async.wait_group 1;\n" ::: "memory");
            __syncthreads();
            issue(s + 2);
            asm volatile("cp.async.commit_group;\n" ::: "memory");
        } else {
            asm volatile("cp.async.wait_group 0;\n" ::: "memory");
            __syncthreads();
        }

        const uint32_t sb = (uint32_t)__cvta_generic_to_shared(
                                sm + (size_t)(s % 3) * GST);
        const uint32_t ah_b = sb;
        const uint32_t al_b = sb + 2 * G_A;
        const uint32_t bh_b = sb + 4 * G_A;
        const uint32_t bl_b = sb + 6 * G_A;

        #pragma unroll
        for (int ks = 0; ks < GKC; ks += 16) {
            uint32_t ah[2][4], al[2][4];
            #pragma unroll
            for (int mf = 0; mf < 2; ++mf) {
                LDSM_X4(ah[mf][0], ah[mf][1], ah[mf][2], ah[mf][3],
                        ah_b + a_off[mf] + ks * 2);
                LDSM_X4(al[mf][0], al[mf][1], al[mf][2], al[mf][3],
                        al_b + a_off[mf] + ks * 2);
            }
            uint32_t bh[4][4], bl[4][4];
            #pragma unroll
            for (int n2 = 0; n2 < 4; ++n2) {
                LDSM_X4(bh[n2][0], bh[n2][1], bh[n2][2], bh[n2][3],
                        bh_b + b_off[n2] + ks * 2);
                LDSM_X4(bl[n2][0], bl[n2][1], bl[n2][2], bl[n2][3],
                        bl_b + b_off[n2] + ks * 2);
            }
            #pragma unroll
            for (int mf = 0; mf < 2; ++mf) {
                #pragma unroll
                for (int n2 = 0; n2 < 4; ++n2) {
                    MMA_BF16(acc[mf][n2 * 2 + 0], ah[mf], bh[n2][0], bh[n2][2]);
                    MMA_BF16(acc[mf][n2 * 2 + 1], ah[mf], bh[n2][1], bh[n2][3]);
                    MMA_BF16(acc[mf][n2 * 2 + 0], ah[mf], bl[n2][0], bl[n2][2]);
                    MMA_BF16(acc[mf][n2 * 2 + 1], ah[mf], bl[n2][1], bl[n2][3]);
                    MMA_BF16(acc[mf][n2 * 2 + 0], al[mf], bh[n2][0], bh[n2][2]);
                    MMA_BF16(acc[mf][n2 * 2 + 1], al[mf], bh[n2][1], bh[n2][3]);
                }
            }
        }
    }

    #pragma unroll
    for (int mf = 0; mf < 2; ++mf) {
        const int row0 = bm + wm * 32 + mf * 16 + g;
        #pragma unroll
        for (int nf = 0; nf < 8; ++nf) {
            const int col = bn + wn * 64 + nf * 8 + tg * 2;
            const float b0 = bias[col], b1 = bias[col + 1];
            float v0 = acc[mf][nf][0] + b0, v1 = acc[mf][nf][1] + b1;
            float v2 = acc[mf][nf][2] + b0, v3 = acc[mf][nf][3] + b1;
            if (relu) {
                v0 = fmaxf(v0, 0.f); v1 = fmaxf(v1, 0.f);
                v2 = fmaxf(v2, 0.f); v3 = fmaxf(v3, 0.f);
            }
            *(float2*)&C[(size_t)row0 * N + col]       = make_float2(v0, v1);
            *(float2*)&C[(size_t)(row0 + 8) * N + col] = make_float2(v2, v3);
        }
    }
}

__global__ __launch_bounds__(256, 1)
void mma_gemm2(const __nv_bfloat16* __restrict__ Ahi,
               const __nv_bfloat16* __restrict__ Alo, int lda,
               const __nv_bfloat16* __restrict__ Bhi,
               const __nv_bfloat16* __restrict__ Blo,
               const float* __restrict__ bias, float* __restrict__ C,
               int N, int K, int relu)
{
    extern __shared__ __align__(16) char smraw[];
    mma_gemm_body(Ahi, Alo, lda, Bhi, Blo, bias, C, N, K, relu,
                  blockIdx.y << 7, blockIdx.x << 7, smraw);
}

// merged 3-modality projection: grid (2, 64, 3)
__global__ __launch_bounds__(256, 1)
void proj3(const __nv_bfloat16* __restrict__ hh,
           const __nv_bfloat16* __restrict__ hl,
           const __nv_bfloat16* __restrict__ wch,
           const __nv_bfloat16* __restrict__ wcl,
           const float* __restrict__ bg, const float* __restrict__ b2,
           const float* __restrict__ b3,
           float* __restrict__ gp, float* __restrict__ d2p,
           float* __restrict__ d3p)
{
    extern __shared__ __align__(16) char smraw[];
    const int m = blockIdx.z;
    const __nv_bfloat16 *Ah, *Al, *Bh, *Bl;
    const float* bias; float* C; int K;
    if (m == 0) { Ah = hh;        Al = hl;        Bh = wch + OFF_WG; Bl = wcl + OFF_WG;
                  bias = bg; C = gp;  K = 512; }
    else if (m == 1) { Ah = hh + 512;  Al = hl + 512;  Bh = wch + OFF_W2; Bl = wcl + OFF_W2;
                  bias = b2; C = d2p; K = 768; }
    else { Ah = hh + 1280; Al = hl + 1280; Bh = wch + OFF_W3; Bl = wcl + OFF_W3;
                  bias = b3; C = d3p; K = 1024; }
    mma_gemm_body(Ah, Al, DCAT, Bh, Bl, bias, C, 256, K, 0,
                  blockIdx.y << 7, blockIdx.x << 7, smraw);
}

// ---------------------------------------------------------------------------
// LayerNorm + ReLU + bf16 hi/lo split.
// ---------------------------------------------------------------------------
__global__ __launch_bounds__(256)
void ln_relu(const float* __restrict__ lgw, const float* __restrict__ lgb,
             const float* __restrict__ l2w, const float* __restrict__ l2b,
             const float* __restrict__ l3w, const float* __restrict__ l3b)
{
    const int idx = blockIdx.x;
    const int mod = idx >> 13;
    const int row = idx & 8191;
    const float* buf; const float* w; const float* b;
    if (mod == 0)      { buf = g_p;  w = lgw; b = lgb; }
    else if (mod == 1) { buf = d2_p; w = l2w; b = l2b; }
    else               { buf = d3_p; w = l3w; b = l3b; }

    const int t = threadIdx.x;
    const float v = buf[(size_t)row * DFT + t];
    float s = v, q = v * v;
    #pragma unroll
    for (int o = 16; o > 0; o >>= 1) {
        s += __shfl_down_sync(0xffffffffu, s, o);
        q += __shfl_down_sync(0xffffffffu, q, o);
    }
    __shared__ float ss[8], qq[8];
    __shared__ float mu_s, rstd_s;
    if ((t & 31) == 0) { ss[t >> 5] = s; qq[t >> 5] = q; }
    __syncthreads();
    if (t == 0) {
        float S = 0.f, Q = 0.f;
        #pragma unroll
        for (int i = 0; i < 8; ++i) { S += ss[i]; Q += qq[i]; }
        const float mu  = S * (1.f / 256.f);
        const float var = Q * (1.f / 256.f) - mu * mu;
        mu_s = mu; rstd_s = rsqrtf(var + 1e-5f);
    }
    __syncthreads();
    const float o  = (v - mu_s) * rstd_s * w[t] + b[t];
    const float oo = fmaxf(o, 0.f);
    const __nv_bfloat16 hi = __float2bfloat16(oo);
    A_hi[mod][(size_t)row * DFT + t] = hi;
    A_lo[mod][(size_t)row * DFT + t] = __float2bfloat16(oo - __bfloat162float(hi));
}

// ---------------------------------------------------------------------------
// beta = softmax(a1 @ Wa2.T + ba2).
// ---------------------------------------------------------------------------
__global__ __launch_bounds__(128)
void beta_kernel(const float* __restrict__ Wa2, const float* __restrict__ ba2)
{
    const int row = blockIdx.x;
    __shared__ float sh[AH];
    __shared__ float logits[RNK];
    const int t = threadIdx.x;
    #pragma unroll
    for (int i = 0; i < 4; ++i)
        sh[t + i * 128] = a1_g[(size_t)row * AH + t + i * 128];
    __syncthreads();

    const int r = t >> 3;
    const int l = t & 7;
    float s = 0.f;
    for (int j = l; j < AH; j += 8)
        s = fmaf(sh[j], Wa2[r * AH + j], s);
    s += __shfl_down_sync(0xffffffffu, s, 4);
    s += __shfl_down_sync(0xffffffffu, s, 2);
    s += __shfl_down_sync(0xffffffffu, s, 1);
    if (l == 0) logits[r] = s + ba2[r];
    __syncthreads();
    if (t == 0) {
        float mx = logits[0];
        #pragma unroll
        for (int i = 1; i < RNK; ++i) mx = fmaxf(mx, logits[i]);
        float e[RNK], den = 0.f;
        #pragma unroll
        for (int i = 0; i < RNK; ++i) { e[i] = expf(logits[i] - mx); den += e[i]; }
        const float inv = 1.f / den;
        #pragma unroll
        for (int i = 0; i < RNK; ++i)
            beta_g[(size_t)row * RNK + i] = e[i] * inv;
    }
}

// ---------------------------------------------------------------------------
// fuse_mma3s: trilinear + beta contraction, 128x128 tile, 512 threads,
// SW128-swizzled smem, 2-stage ring, z accumulated in SMEM (no global RMW).
//   z[b,d] = sum_r beta[b,r] * (g·U_r) * (d2·V_r) * (d3·S_r)
// ---------------------------------------------------------------------------
#define F3_ARR  16384u                   // bytes per array (128 rows x 128B)
#define F3_STG  65536u                   // 4 arrays per stage
#define F3RING  (2 * 65536)              // 2-stage ring
#define F3ZPIT  132
#define F3Z     (128 * F3ZPIT * 4)       // 67584 bytes
#define F3SMEM  (F3RING + F3Z)           // 198656 bytes
#define F3NST   (RNK * 3 * 4)            // 192 stages

__global__ __launch_bounds__(512, 1)
void fuse_mma3s(float* __restrict__ z)
{
    extern __shared__ __align__(16) char smraw[];
    float* zs = (float*)(smraw + F3RING);
    __shared__ float Bes[128][17];

    const int bm   = blockIdx.y << 7;
    const int bn   = blockIdx.x << 7;
    const int tid  = threadIdx.x;
    const int lane = tid & 31, wid = tid >> 5;
    const int wm   = wid & 3,  wn  = wid >> 2;     // 4 x 4 warps
    const int g    = lane >> 2, tg = lane & 3;

    for (int i = tid; i < 128 * RNK; i += 512)
        Bes[i >> 4][i & 15] = beta_g[(size_t)(bm + (i >> 4)) * RNK + (i & 15)];

    const uint32_t smbase = (uint32_t)__cvta_generic_to_shared(smraw);

    auto issue = [&](int s) {
        const int r2  = s / 12;
        const int rem = s % 12;
        const int m2  = rem >> 2;
        const int kc  = (rem & 3) << 6;
        const uint32_t sb = smbase + (uint32_t)(s & 1) * F3_STG;
        #pragma unroll
        for (int i = 0; i < 8; ++i) {
            const int c   = i * 512 + tid;      // 0..4095
            const int arr = c >> 10;
            const int idx = c & 1023;
            const int row = idx >> 3, seg = idx & 7;
            const uint32_t dst = sb + (uint32_t)arr * F3_ARR + row * 128
                               + ((seg * 16) ^ ((row & 7) << 4));
            const __nv_bfloat16* src;
            if (arr == 0)      src = &A_hi[m2][(size_t)(bm + row) * DFT + kc + seg * 8];
            else if (arr == 1) src = &A_lo[m2][(size_t)(bm + row) * DFT + kc + seg * 8];
            else if (arr == 2) src = &W_hi[m2][(size_t)(r2 * DFT + bn + row) * DFT + kc + seg * 8];
            else               src = &W_lo[m2][(size_t)(r2 * DFT + bn + row) * DFT + kc + seg * 8];
            asm volatile("cp.async.cg.shared.global [%0], [%1], 16;\n"
                         :: "r"(dst), "l"(src));
        }
    };

    issue(0);
    asm volatile("cp.async.commit_group;\n" ::: "memory");

    // ldmatrix addressing: addr = arr_base + row*128 + (kt ^ ((row&7)<<4))
    const int lq = lane & 7, lh = (lane >> 3) & 1, lk = lane >> 4;
    int a_rb[2], a_sw[2], b_rb[2], b_sw[2];
    #pragma unroll
    for (int mf = 0; mf < 2; ++mf) {
        const int wr = wm * 32 + mf * 16 + lq + lh * 8;
        a_rb[mf] = wr * 128; a_sw[mf] = (wr & 7) << 4;
    }
    #pragma unroll
    for (int n2 = 0; n2 < 2; ++n2) {
        const int wc = wn * 32 + n2 * 16 + lq + lh * 8;
        b_rb[n2] = wc * 128; b_sw[n2] = (wc & 7) << 4;
    }

    float acc[2][4][4], prod[2][4][4];
    #pragma unroll
    for (int mf = 0; mf < 2; ++mf)
        #pragma unroll
        for (int nf = 0; nf < 4; ++nf)
            #pragma unroll
            for (int e = 0; e < 4; ++e) acc[mf][nf][e] = 0.f;

    int s = 0;
    for (int r = 0; r < RNK; ++r) {
        #pragma unroll
        for (int mI = 0; mI < 3; ++mI) {
            for (int c4 = 0; c4 < 4; ++c4, ++s) {
                // 2-stage ring: wait for stage s, then prefetch s+1.
                // Slot (s+1)&1 was last read at stage s-1, which all threads
                // finished before this barrier -> safe to overwrite.
                asm volatile("cp.async.wait_group 0;\n" ::: "memory");
                __syncthreads();
                if (s + 1 < F3NST) {
                    issue(s + 1);
                    asm volatile("cp.async.commit_group;\n" ::: "memory");
                }

                const uint32_t sb = smbase + (uint32_t)(s & 1) * F3_STG;
                const uint32_t ah_b = sb;
                const uint32_t al_b = sb + F3_ARR;
                const uint32_t bh_b = sb + 2 * F3_ARR;
                const uint32_t bl_b = sb + 3 * F3_ARR;

                #pragma unroll
                for (int ks = 0; ks < 64; ks += 16) {
                    const int kt = ks * 2 + lk * 16;
                    uint32_t ah[2][4], al[2][4];
                    #pragma unroll
                    for (int mf = 0; mf < 2; ++mf) {
                        LDSM_X4(ah[mf][0], ah[mf][1], ah[mf][2], ah[mf][3],
                                ah_b + a_rb[mf] + (kt ^ a_sw[mf]));
                        LDSM_X4(al[mf][0], al[mf][1], al[mf][2], al[mf][3],
                                al_b + a_rb[mf] + (kt ^ a_sw[mf]));
                    }
                    uint32_t bh[2][4], bl[2][4];
                    #pragma unroll
                    for (int n2 = 0; n2 < 2; ++n2) {
                        LDSM_X4(bh[n2][0], bh[n2][1], bh[n2][2], bh[n2][3],
                                bh_b + b_rb[n2] + (kt ^ b_sw[n2]));
                        LDSM_X4(bl[n2][0], bl[n2][1], bl[n2][2], bl[n2][3],
                                bl_b + b_rb[n2] + (kt ^ b_sw[n2]));
                    }
                    #pragma unroll
                    for (int mf = 0; mf < 2; ++mf) {
                        #pragma unroll
                        for (int n2 = 0; n2 < 2; ++n2) {
                            MMA_BF16(acc[mf][n2 * 2 + 0], ah[mf], bh[n2][0], bh[n2][2]);
                            MMA_BF16(acc[mf][n2 * 2 + 1], ah[mf], bh[n2][1], bh[n2][3]);
                            MMA_BF16(acc[mf][n2 * 2 + 0], ah[mf], bl[n2][0], bl[n2][2]);
                            MMA_BF16(acc[mf][n2 * 2 + 1], ah[mf], bl[n2][1], bl[n2][3]);
                            MMA_BF16(acc[mf][n2 * 2 + 0], al[mf], bh[n2][0], bh[n2][2]);
                            MMA_BF16(acc[mf][n2 * 2 + 1], al[mf], bh[n2][1], bh[n2][3]);
                        }
                    }
                }
            }
            if (mI == 0) {
                #pragma unroll
                for (int mf = 0; mf < 2; ++mf)
                    #pragma unroll
                    for (int nf = 0; nf < 4; ++nf)
                        #pragma unroll
                        for (int e = 0; e < 4; ++e)
                            { prod[mf][nf][e] = acc[mf][nf][e]; acc[mf][nf][e] = 0.f; }
            } else if (mI == 1) {
                #pragma unroll
                for (int mf = 0; mf < 2; ++mf)
                    #pragma unroll
                    for (int nf = 0; nf < 4; ++nf)
                        #pragma unroll
                        for (int e = 0; e < 4; ++e)
                            { prod[mf][nf][e] *= acc[mf][nf][e]; acc[mf][nf][e] = 0.f; }
            } else {
                // rank contribution -> smem z accumulator (thread-exclusive)
                #pragma unroll
                for (int mf = 0; mf < 2; ++mf) {
                    const int rt = wm * 32 + mf * 16 + g;
                    const float b0 = Bes[rt][r];
                    const float b1 = Bes[rt + 8][r];
                    #pragma unroll
                    for (int nf = 0; nf < 4; ++nf) {
                        const int ct = wn * 32 + nf * 8 + tg * 2;
                        float* p0 = zs + rt * F3ZPIT + ct;
                        float* p1 = zs + (rt + 8) * F3ZPIT + ct;
                        const float v0 = b0 * prod[mf][nf][0] * acc[mf][nf][0];
                        const float v1 = b0 * prod[mf][nf][1] * acc[mf][nf][1];
                        const float v2 = b1 * prod[mf][nf][2] * acc[mf][nf][2];
                        const float v3 = b1 * prod[mf][nf][3] * acc[mf][nf][3];
                        if (r == 0) {
                            p0[0] = v0; p0[1] = v1; p1[0] = v2; p1[1] = v3;
                        } else {
                            p0[0] += v0; p0[1] += v1; p1[0] += v2; p1[1] += v3;
                        }
                        #pragma unroll
                        for (int e = 0; e < 4; ++e) acc[mf][nf][e] = 0.f;
                    }
                }
            }
        }
    }

    // epilogue: smem z -> global
    __syncthreads();
    for (int i = tid; i < 128 * 32; i += 512) {
        const int row = i >> 5, c4 = (i & 31) << 2;
        const float4 v = *(const float4*)(zs + row * F3ZPIT + c4);
        *(float4*)&z[(size_t)(bm + row) * DFT + bn + c4] = v;
    }
}

// ---------------------------------------------------------------------------
// Host launcher (graph-capturable; event-forked side stream)
// ---------------------------------------------------------------------------
extern "C" void kernel_launch(void* const* d_in, const int* in_sizes, int n_in,
                              void* d_out, int out_size)
{
    const float* h_g  = (const float*)d_in[0];
    const float* h_2d = (const float*)d_in[1];
    const float* h_3d = (const float*)d_in[2];
    const float* Wg   = (const float*)d_in[3];
    const float* bg   = (const float*)d_in[4];
    const float* W2   = (const float*)d_in[5];
    const float* b2   = (const float*)d_in[6];
    const float* W3   = (const float*)d_in[7];
    const float* b3   = (const float*)d_in[8];
    const float* lgw  = (const float*)d_in[9];
    const float* lgb  = (const float*)d_in[10];
    const float* l2w  = (const float*)d_in[11];
    const float* l2b  = (const float*)d_in[12];
    const float* l3w  = (const float*)d_in[13];
    const float* l3b  = (const float*)d_in[14];
    const float* U    = (const float*)d_in[15];
    const float* V    = (const float*)d_in[16];
    const float* S    = (const float*)d_in[17];
    const float* Wa1  = (const float*)d_in[18];
    const float* ba1  = (const float*)d_in[19];
    const float* Wa2  = (const float*)d_in[20];
    const float* ba2  = (const float*)d_in[21];
    float* z = (float*)d_out;

    float *gp, *d2p, *d3p, *a1p;
    cudaGetSymbolAddress((void**)&gp,  g_p);
    cudaGetSymbolAddress((void**)&d2p, d2_p);
    cudaGetSymbolAddress((void**)&d3p, d3_p);
    cudaGetSymbolAddress((void**)&a1p, a1_g);
    __nv_bfloat16 *whi, *wlo, *hh, *hl, *wch, *wcl;
    cudaGetSymbolAddress((void**)&whi, W_hi);
    cudaGetSymbolAddress((void**)&wlo, W_lo);
    cudaGetSymbolAddress((void**)&hh,  hcat_hi);
    cudaGetSymbolAddress((void**)&hl,  hcat_lo);
    cudaGetSymbolAddress((void**)&wch, wcat_hi);
    cudaGetSymbolAddress((void**)&wcl, wcat_lo);

    static int inited = 0;
    static cudaStream_t s1;
    static cudaEvent_t evF, evA, evJ;
    if (!inited) {
        cudaFuncSetAttribute(fuse_mma3s, cudaFuncAttributeMaxDynamicSharedMemorySize,
                             F3SMEM);
        cudaFuncSetAttribute(mma_gemm2, cudaFuncAttributeMaxDynamicSharedMemorySize,
                             GSMEM);
        cudaFuncSetAttribute(proj3, cudaFuncAttributeMaxDynamicSharedMemorySize,
                             GSMEM);
        cudaStreamCreateWithFlags(&s1, cudaStreamNonBlocking);
        cudaEventCreateWithFlags(&evF, cudaEventDisableTiming);
        cudaEventCreateWithFlags(&evA, cudaEventDisableTiming);
        cudaEventCreateWithFlags(&evJ, cudaEventDisableTiming);
        inited = 1;
    }

    // ---- main stream: input (hcat) splits ----
    cudaEventRecord(evF, 0);
    split_strided<<<NB * 512  / 256, 256>>>(h_g,  512,  0);
    split_strided<<<NB * 768  / 256, 256>>>(h_2d, 768,  512);
    split_strided<<<NB * 1024 / 256, 256>>>(h_3d, 1024, 1280);
    cudaEventRecord(evA, 0);

    // ---- side stream: Wa1 split, Wa1 GEMM, beta ----
    cudaStreamWaitEvent(s1, evF, 0);
    splitw<<<(512 * 2304) / 256, 256, 0, s1>>>(Wa1, wch + OFF_WA1, wcl + OFF_WA1,
                                               512 * 2304);
    cudaStreamWaitEvent(s1, evA, 0);
    mma_gemm2<<<dim3(4, 64), 256, GSMEM, s1>>>(hh, hl, DCAT,
        wch + OFF_WA1, wcl + OFF_WA1, ba1, a1p, 512, 2304, 1);
    beta_kernel<<<NB, 128, 0, s1>>>(Wa2, ba2);
    cudaEventRecord(evJ, s1);

    // ---- main stream: U/V/S splits, projection weights, merged proj, LN ----
    splitw<<<WSZ / 256, 256>>>(U, whi + 0 * WSZ, wlo + 0 * WSZ, WSZ);
    splitw<<<WSZ / 256, 256>>>(V, whi + 1 * WSZ, wlo + 1 * WSZ, WSZ);
    splitw<<<WSZ / 256, 256>>>(S, whi + 2 * WSZ, wlo + 2 * WSZ, WSZ);
    splitw<<<(256 * 512)  / 256, 256>>>(Wg,  wch + OFF_WG,  wcl + OFF_WG,  256 * 512);
    splitw<<<(256 * 768)  / 256, 256>>>(W2,  wch + OFF_W2,  wcl + OFF_W2,  256 * 768);
    splitw<<<(256 * 1024) / 256, 256>>>(W3,  wch + OFF_W3,  wcl + OFF_W3,  256 * 1024);
    proj3<<<dim3(2, 64, 3), 256, GSMEM>>>(hh, hl, wch, wcl, bg, b2, b3,
                                          gp, d2p, d3p);
    ln_relu<<<3 * NB, 256>>>(lgw, lgb, l2w, l2b, l3w, l3b);

    // ---- join and run the fused trilinear (128 CTAs, one wave) ----
    cudaStreamWaitEvent(0, evJ, 0);
    fuse_mma3s<<<dim3(2, 64), 512, F3SMEM>>>(z);
}